// round 1
// baseline (speedup 1.0000x reference)
#include <cuda_runtime.h>

#define BATCH 4
#define SEQ   1024
#define DM    1024
#define HEADS 16
#define HD    64
#define BH    (BATCH*HEADS)

// ---------------- scratch (device globals; no allocs allowed) ----------------
__device__ float g_Q[BATCH*SEQ*DM];                 // 16 MB
__device__ float g_K[BATCH*SEQ*DM];                 // 16 MB
__device__ float g_V[BATCH*SEQ*DM];                 // 16 MB
__device__ float g_O[BATCH*SEQ*DM];                 // 16 MB  (already [b, l, h*64+dd] layout)
__device__ float g_QEr[(long long)BH*SEQ*SEQ];      // 256 MB
__device__ float g_S[(long long)BH*SEQ*SEQ];        // 256 MB

// ---------------- shared helpers ----------------
__device__ __forceinline__ void st_tr(float (*s)[68], int k, int r, float4 v) {
    s[k+0][r] = v.x; s[k+1][r] = v.y; s[k+2][r] = v.z; s[k+3][r] = v.w;
}

__device__ __forceinline__ void mm16(const float (*a_s)[68], const float (*b_s)[68],
                                     float acc[4][4], int tx, int ty) {
    #pragma unroll
    for (int kk = 0; kk < 16; kk++) {
        const float4 a = *(const float4*)&a_s[kk][ty << 2];
        const float4 b = *(const float4*)&b_s[kk][tx << 2];
        const float av[4] = {a.x, a.y, a.z, a.w};
        const float bv[4] = {b.x, b.y, b.z, b.w};
        #pragma unroll
        for (int ii = 0; ii < 4; ii++)
            #pragma unroll
            for (int jj = 0; jj < 4; jj++)
                acc[ii][jj] = fmaf(av[ii], bv[jj], acc[ii][jj]);
    }
}

// ---------------- generic NN SGEMM: C[M,N] = A[M,K] @ W[K,N], row-major ----------------
__global__ __launch_bounds__(256) void sgemm_nn(const float* __restrict__ A,
                                                const float* __restrict__ W,
                                                float* __restrict__ C,
                                                int M, int N, int K)
{
    __shared__ float a_s[16][68];
    __shared__ float b_s[16][68];
    const int tid = threadIdx.x;
    const int tx = tid & 15, ty = tid >> 4;
    const int m0 = blockIdx.y << 6, n0 = blockIdx.x << 6;
    const int ar = tid >> 2, ac = (tid & 3) << 2;     // A tile loader: 64 rows x 16 k
    const int bwr = tid >> 4, bwc = (tid & 15) << 2;  // B tile loader: 16 k x 64 cols
    float acc[4][4] = {};

    for (int k0 = 0; k0 < K; k0 += 16) {
        const float4 av = *(const float4*)(A + (size_t)(m0 + ar) * K + k0 + ac);
        st_tr(a_s, ac, ar, av);
        *(float4*)&b_s[bwr][bwc] = *(const float4*)(W + (size_t)(k0 + bwr) * N + n0 + bwc);
        __syncthreads();
        mm16(a_s, b_s, acc, tx, ty);
        __syncthreads();
    }
    #pragma unroll
    for (int i = 0; i < 4; i++) {
        *(float4*)(C + (size_t)(m0 + (ty << 2) + i) * N + n0 + (tx << 2)) =
            make_float4(acc[i][0], acc[i][1], acc[i][2], acc[i][3]);
    }
}

// ---------------- QEr[bh, r, e] = sum_dd q(b,h,r,dd) * Er[e, dd]   (NT, K=64) ----------
__global__ __launch_bounds__(256) void qer_kernel(const float* __restrict__ Er)
{
    __shared__ float a_s[16][68];
    __shared__ float b_s[16][68];
    const int tid = threadIdx.x;
    const int tx = tid & 15, ty = tid >> 4;
    const int bh = blockIdx.z, b = bh >> 4, h = bh & 15;
    const int r0 = blockIdx.y << 6, e0 = blockIdx.x << 6;
    const int ar = tid >> 2, ac = (tid & 3) << 2;
    float acc[4][4] = {};

    const int i = r0 + ar;  // q row gather (plain-reshape head split)
    const float* qrow = g_Q + (size_t)(b * SEQ + h * HD + (i >> 4)) * DM + ((i & 15) << 6);
    const float* erow = Er + (size_t)(e0 + ar) * HD;

    for (int k0 = 0; k0 < HD; k0 += 16) {
        st_tr(a_s, ac, ar, *(const float4*)(qrow + k0 + ac));
        st_tr(b_s, ac, ar, *(const float4*)(erow + k0 + ac));   // b_s[k][e]
        __syncthreads();
        mm16(a_s, b_s, acc, tx, ty);
        __syncthreads();
    }
    #pragma unroll
    for (int ii = 0; ii < 4; ii++) {
        *(float4*)(g_QEr + (size_t)(bh * SEQ + r0 + (ty << 2) + ii) * SEQ + e0 + (tx << 2)) =
            make_float4(acc[ii][0], acc[ii][1], acc[ii][2], acc[ii][3]);
    }
}

// ---------------- S = (q @ k_t + Srel(skew)) / 8 ----------------------------------------
__global__ __launch_bounds__(256) void score_kernel()
{
    __shared__ float a_s[16][68];
    __shared__ float b_s[16][68];
    const int tid = threadIdx.x;
    const int tx = tid & 15, ty = tid >> 4;
    const int bh = blockIdx.z, b = bh >> 4, h = bh & 15;
    const int i0 = blockIdx.y << 6, j0 = blockIdx.x << 6;
    const int ar = tid >> 2, ac = (tid & 3) << 2;
    const int bwr = tid >> 4, bwc = (tid & 15) << 2;
    float acc[4][4] = {};

    const int i = i0 + ar;
    const float* qrow  = g_Q + (size_t)(b * SEQ + h * HD + (i >> 4)) * DM + ((i & 15) << 6);
    const float* kbase = g_K + (size_t)(b * SEQ + h * HD) * DM;   // k_t[b,h,dd,j] = K[b, h*64+dd, j]

    for (int k0 = 0; k0 < HD; k0 += 16) {
        st_tr(a_s, ac, ar, *(const float4*)(qrow + k0 + ac));
        *(float4*)&b_s[bwr][bwc] = *(const float4*)(kbase + (size_t)(k0 + bwr) * DM + j0 + bwc);
        __syncthreads();
        mm16(a_s, b_s, acc, tx, ty);
        __syncthreads();
    }

    // epilogue: add skewed relative bias, scale by 1/sqrt(64)
    #pragma unroll
    for (int ii = 0; ii < 4; ii++) {
        const int ig = i0 + (ty << 2) + ii;
        #pragma unroll
        for (int jj = 0; jj < 4; jj++) {
            const int c = j0 + (tx << 2) + jj;
            float rel;
            if (c <= ig)
                rel = g_QEr[(size_t)(bh * SEQ + ig) * SEQ + (SEQ - 1 + c - ig)];
            else if (c == ig + 1)
                rel = 0.0f;
            else  // c > ig+1  (implies ig+1 <= 1022, in-bounds)
                rel = g_QEr[(size_t)(bh * SEQ + ig + 1) * SEQ + (c - ig - 2)];
            g_S[(size_t)(bh * SEQ + ig) * SEQ + c] = (acc[ii][jj] + rel) * 0.125f;
        }
    }
}

// ---------------- row softmax over last dim of g_S [BH*SEQ rows of SEQ] -----------------
__global__ __launch_bounds__(256) void softmax_kernel()
{
    float* p = g_S + (size_t)blockIdx.x * SEQ;
    const int t = threadIdx.x;
    float x0 = p[t], x1 = p[t + 256], x2 = p[t + 512], x3 = p[t + 768];

    __shared__ float red[256];
    red[t] = fmaxf(fmaxf(x0, x1), fmaxf(x2, x3));
    __syncthreads();
    for (int s = 128; s > 0; s >>= 1) {
        if (t < s) red[t] = fmaxf(red[t], red[t + s]);
        __syncthreads();
    }
    const float m = red[0];
    __syncthreads();

    x0 = __expf(x0 - m); x1 = __expf(x1 - m); x2 = __expf(x2 - m); x3 = __expf(x3 - m);
    red[t] = x0 + x1 + x2 + x3;
    __syncthreads();
    for (int s = 128; s > 0; s >>= 1) {
        if (t < s) red[t] += red[t + s];
        __syncthreads();
    }
    const float inv = 1.0f / red[0];
    p[t] = x0 * inv; p[t + 256] = x1 * inv; p[t + 512] = x2 * inv; p[t + 768] = x3 * inv;
}

// ---------------- O[b, i, h*64+dd] = sum_j attn[bh,i,j] * v(b,h,j,dd) -------------------
__global__ __launch_bounds__(256) void av_kernel()
{
    __shared__ float a_s[16][68];
    __shared__ float b_s[16][68];
    const int tid = threadIdx.x;
    const int tx = tid & 15, ty = tid >> 4;
    const int bh = blockIdx.y, b = bh >> 4, h = bh & 15;
    const int i0 = blockIdx.x << 6;
    const int ar = tid >> 2, ac = (tid & 3) << 2;
    const int bwr = tid >> 4, bwc = (tid & 15) << 2;
    float acc[4][4] = {};

    for (int j0 = 0; j0 < SEQ; j0 += 16) {
        st_tr(a_s, ac, ar,
              *(const float4*)(g_S + (size_t)(bh * SEQ + i0 + ar) * SEQ + j0 + ac));
        const int j = j0 + bwr;  // v row gather (plain-reshape head split)
        const float* vrow = g_V + (size_t)(b * SEQ + h * HD + (j >> 4)) * DM + ((j & 15) << 6);
        *(float4*)&b_s[bwr][bwc] = *(const float4*)(vrow + bwc);
        __syncthreads();
        mm16(a_s, b_s, acc, tx, ty);
        __syncthreads();
    }
    #pragma unroll
    for (int ii = 0; ii < 4; ii++) {
        *(float4*)(g_O + (size_t)(b * SEQ + i0 + (ty << 2) + ii) * DM + h * HD + (tx << 2)) =
            make_float4(acc[ii][0], acc[ii][1], acc[ii][2], acc[ii][3]);
    }
}

// ---------------- launch ----------------
extern "C" void kernel_launch(void* const* d_in, const int* in_sizes, int n_in,
                              void* d_out, int out_size)
{
    const float* query = (const float*)d_in[0];
    const float* key   = (const float*)d_in[1];
    const float* value = (const float*)d_in[2];
    const float* WQ    = (const float*)d_in[3];
    const float* WK    = (const float*)d_in[4];
    const float* WV    = (const float*)d_in[5];
    const float* Er    = (const float*)d_in[6];
    const float* WM    = (const float*)d_in[7];
    float* out = (float*)d_out;

    static float *pQ = nullptr, *pK = nullptr, *pV = nullptr, *pO = nullptr;
    if (!pQ) {
        cudaGetSymbolAddress((void**)&pQ, g_Q);
        cudaGetSymbolAddress((void**)&pK, g_K);
        cudaGetSymbolAddress((void**)&pV, g_V);
        cudaGetSymbolAddress((void**)&pO, g_O);
    }

    const dim3 blk(256);
    const dim3 gProj(DM / 64, (BATCH * SEQ) / 64);        // (16, 64)
    const dim3 gHead(SEQ / 64, SEQ / 64, BH);             // (16, 16, 64)

    sgemm_nn<<<gProj, blk>>>(query, WQ, pQ, BATCH * SEQ, DM, DM);
    sgemm_nn<<<gProj, blk>>>(key,   WK, pK, BATCH * SEQ, DM, DM);
    sgemm_nn<<<gProj, blk>>>(value, WV, pV, BATCH * SEQ, DM, DM);
    qer_kernel<<<gHead, blk>>>(Er);
    score_kernel<<<gHead, blk>>>();
    softmax_kernel<<<BH * SEQ, blk>>>();
    av_kernel<<<dim3(SEQ / 64, BH), blk>>>();
    sgemm_nn<<<gProj, blk>>>(pO, WM, out, BATCH * SEQ, DM, DM);
}

// round 3
// speedup vs baseline: 1.1453x; 1.1453x over previous
#include <cuda_runtime.h>
#include <cuda_bf16.h>

#define BATCH 4
#define SEQ   1024
#define DM    1024
#define HEADS 16
#define HD    64
#define BH    (BATCH*HEADS)

// ---------------- scratch (device globals; no allocs allowed) ----------------
__device__ float g_Q[BATCH*SEQ*DM];                 // 16 MB
__device__ float g_K[BATCH*SEQ*DM];                 // 16 MB
__device__ float g_V[BATCH*SEQ*DM];                 // 16 MB
__device__ float g_O[BATCH*SEQ*DM];                 // 16 MB
__device__ float g_QEr[(long long)BH*SEQ*SEQ];      // 256 MB
__device__ float g_S[(long long)BH*SEQ*SEQ];        // 256 MB

// ---------------- helpers ----------------
// split a float2 into packed bf16x2 hi + lo (x - bf16(x) is exact)
__device__ __forceinline__ void split2(float2 v, unsigned &h, unsigned &l) {
    __nv_bfloat162 bh = __float22bfloat162_rn(v);
    float2 back = __bfloat1622float2(bh);
    __nv_bfloat162 bl = __float22bfloat162_rn(make_float2(v.x - back.x, v.y - back.y));
    h = *(unsigned*)&bh;
    l = *(unsigned*)&bl;
}

__device__ __forceinline__ void mma_bf16(float c[4], const unsigned a[4], const unsigned b[2]) {
    asm volatile(
        "mma.sync.aligned.m16n8k16.row.col.f32.bf16.bf16.f32 "
        "{%0,%1,%2,%3},{%4,%5,%6,%7},{%8,%9},{%0,%1,%2,%3};\n"
        : "+f"(c[0]), "+f"(c[1]), "+f"(c[2]), "+f"(c[3])
        : "r"(a[0]), "r"(a[1]), "r"(a[2]), "r"(a[3]), "r"(b[0]), "r"(b[1]));
}

// One BK=32 slab (2 k16 sub-slabs). Ah/Al: [rows][20] packed k-pairs (pair p = k 2p,2p+1).
// Bh/Bl: [cols][20] packed k-pairs. 3 MMAs per tile: hi*hi + lo*hi + hi*lo.
template<int TM, int TN>
__device__ __forceinline__ void mma32(const unsigned (*Ah)[20], const unsigned (*Al)[20],
                                      const unsigned (*Bh)[20], const unsigned (*Bl)[20],
                                      float (*acc)[TN][4], int warp_m, int warp_n, int lane) {
    const int qr = lane >> 2, qc = lane & 3;
    #pragma unroll
    for (int s = 0; s < 2; s++) {
        const int kp = qc + 8 * s;
        unsigned ah[TM][4], al[TM][4], bh[TN][2], bl[TN][2];
        #pragma unroll
        for (int tm = 0; tm < TM; tm++) {
            const int m = warp_m + tm * 16 + qr;
            ah[tm][0] = Ah[m][kp];     ah[tm][1] = Ah[m + 8][kp];
            ah[tm][2] = Ah[m][kp + 4]; ah[tm][3] = Ah[m + 8][kp + 4];
            al[tm][0] = Al[m][kp];     al[tm][1] = Al[m + 8][kp];
            al[tm][2] = Al[m][kp + 4]; al[tm][3] = Al[m + 8][kp + 4];
        }
        #pragma unroll
        for (int tn = 0; tn < TN; tn++) {
            const int n = warp_n + tn * 8 + qr;
            bh[tn][0] = Bh[n][kp]; bh[tn][1] = Bh[n][kp + 4];
            bl[tn][0] = Bl[n][kp]; bl[tn][1] = Bl[n][kp + 4];
        }
        #pragma unroll
        for (int tm = 0; tm < TM; tm++)
            #pragma unroll
            for (int tn = 0; tn < TN; tn++) {
                mma_bf16(acc[tm][tn], ah[tm], bh[tn]);
                mma_bf16(acc[tm][tn], al[tm], bh[tn]);
                mma_bf16(acc[tm][tn], ah[tm], bl[tn]);
            }
    }
}

__device__ __forceinline__ const float* q_row(int b, int h, int i) {
    return g_Q + (size_t)(b * SEQ + h * HD + (i >> 4)) * DM + ((i & 15) << 6);
}
__device__ __forceinline__ const float* v_row(int b, int h, int j) {
    return g_V + (size_t)(b * SEQ + h * HD + (j >> 4)) * DM + ((j & 15) << 6);
}

// store 16 consecutive k floats (row-major) as 8 packed pairs into Ah/Al[row][p0..p0+7]
__device__ __forceinline__ void store_rowmajor16(const float* src, unsigned (*Ah)[20],
                                                 unsigned (*Al)[20], int row, int p0) {
    unsigned h[8], l[8];
    #pragma unroll
    for (int i = 0; i < 4; i++) {
        const float4 x = *(const float4*)(src + 4 * i);
        split2(make_float2(x.x, x.y), h[2 * i], l[2 * i]);
        split2(make_float2(x.z, x.w), h[2 * i + 1], l[2 * i + 1]);
    }
    *(uint4*)&Ah[row][p0]     = make_uint4(h[0], h[1], h[2], h[3]);
    *(uint4*)&Ah[row][p0 + 4] = make_uint4(h[4], h[5], h[6], h[7]);
    *(uint4*)&Al[row][p0]     = make_uint4(l[0], l[1], l[2], l[3]);
    *(uint4*)&Al[row][p0 + 4] = make_uint4(l[4], l[5], l[6], l[7]);
}

// store a 2(k)x4(n) chunk from two k-rows into Bh/Bl[c..c+3][kp]
__device__ __forceinline__ void store_kmajor2x4(float4 x0, float4 x1, unsigned (*Bh)[20],
                                                unsigned (*Bl)[20], int c, int kp) {
    unsigned h, l;
    split2(make_float2(x0.x, x1.x), h, l); Bh[c][kp] = h;     Bl[c][kp] = l;
    split2(make_float2(x0.y, x1.y), h, l); Bh[c + 1][kp] = h; Bl[c + 1][kp] = l;
    split2(make_float2(x0.z, x1.z), h, l); Bh[c + 2][kp] = h; Bl[c + 2][kp] = l;
    split2(make_float2(x0.w, x1.w), h, l); Bh[c + 3][kp] = h; Bl[c + 3][kp] = l;
}

// ---------------- generic NN GEMM: C[M,N] = A[M,K] @ W[K,N] ----------------
__global__ __launch_bounds__(256) void bf_gemm_nn(const float* __restrict__ A,
                                                  const float* __restrict__ W,
                                                  float* __restrict__ C,
                                                  int M, int N, int K)
{
    __shared__ unsigned Ah[128][20], Al[128][20], Bh[128][20], Bl[128][20];
    const int tid = threadIdx.x, lane = tid & 31, w = tid >> 5;
    const int m0 = blockIdx.y << 7, n0 = blockIdx.x << 7;
    const int warp_m = (w >> 2) * 64, warp_n = (w & 3) * 32;
    const int am = tid >> 1, ako = (tid & 1) << 4;
    const int bkp = tid & 15, bcg = tid >> 4;
    float acc[4][4][4] = {};

    for (int k0 = 0; k0 < K; k0 += 32) {
        store_rowmajor16(A + (size_t)(m0 + am) * K + k0 + ako, Ah, Al, am, ako >> 1);
        #pragma unroll
        for (int rep = 0; rep < 2; rep++) {
            const int c = (bcg + 16 * rep) << 2;
            const float* p = W + (size_t)(k0 + 2 * bkp) * N + n0 + c;
            store_kmajor2x4(*(const float4*)p, *(const float4*)(p + N), Bh, Bl, c, bkp);
        }
        __syncthreads();
        mma32<4, 4>(Ah, Al, Bh, Bl, acc, warp_m, warp_n, lane);
        __syncthreads();
    }
    const int qr = lane >> 2, qc = lane & 3;
    #pragma unroll
    for (int tm = 0; tm < 4; tm++)
        #pragma unroll
        for (int tn = 0; tn < 4; tn++) {
            const int r = m0 + warp_m + tm * 16 + qr;
            const int cN = n0 + warp_n + tn * 8 + qc * 2;
            *(float2*)(C + (size_t)r * N + cN)       = make_float2(acc[tm][tn][0], acc[tm][tn][1]);
            *(float2*)(C + (size_t)(r + 8) * N + cN) = make_float2(acc[tm][tn][2], acc[tm][tn][3]);
        }
}

// ---------------- QEr[bh, r, e] = sum_dd q(b,h,r,dd) * Er[e, dd] ----------------
__global__ __launch_bounds__(256) void qer_tc(const float* __restrict__ Er)
{
    __shared__ unsigned Ah[128][20], Al[128][20], Bh[128][20], Bl[128][20];
    const int tid = threadIdx.x, lane = tid & 31, w = tid >> 5;
    const int bh = blockIdx.z, b = bh >> 4, h = bh & 15;
    const int r0 = blockIdx.y << 7, e0 = blockIdx.x << 7;
    const int warp_m = (w >> 2) * 64, warp_n = (w & 3) * 32;
    const int am = tid >> 1, ako = (tid & 1) << 4;
    float acc[4][4][4] = {};

    for (int k0 = 0; k0 < HD; k0 += 32) {
        store_rowmajor16(q_row(b, h, r0 + am) + k0 + ako, Ah, Al, am, ako >> 1);
        // Er rows are k-contiguous too: B[k][e] with e as "row" of Er
        store_rowmajor16(Er + (size_t)(e0 + am) * HD + k0 + ako, Bh, Bl, am, ako >> 1);
        __syncthreads();
        mma32<4, 4>(Ah, Al, Bh, Bl, acc, warp_m, warp_n, lane);
        __syncthreads();
    }
    const int qr = lane >> 2, qc = lane & 3;
    #pragma unroll
    for (int tm = 0; tm < 4; tm++)
        #pragma unroll
        for (int tn = 0; tn < 4; tn++) {
            const int r = r0 + warp_m + tm * 16 + qr;
            const int e = e0 + warp_n + tn * 8 + qc * 2;
            *(float2*)(g_QEr + (size_t)(bh * SEQ + r) * SEQ + e)     = make_float2(acc[tm][tn][0], acc[tm][tn][1]);
            *(float2*)(g_QEr + (size_t)(bh * SEQ + r + 8) * SEQ + e) = make_float2(acc[tm][tn][2], acc[tm][tn][3]);
        }
}

// ---------------- S = (q @ k_t + Srel(skew)) / 8 ----------------
__device__ __forceinline__ float skew_rel(int bh, int ig, int c) {
    if (c <= ig)
        return g_QEr[(size_t)(bh * SEQ + ig) * SEQ + (SEQ - 1 + c - ig)];
    else if (c == ig + 1)
        return 0.0f;
    else
        return g_QEr[(size_t)(bh * SEQ + ig + 1) * SEQ + (c - ig - 2)];
}

__global__ __launch_bounds__(256) void score_tc()
{
    __shared__ unsigned Ah[128][20], Al[128][20], Bh[128][20], Bl[128][20];
    const int tid = threadIdx.x, lane = tid & 31, w = tid >> 5;
    const int bh = blockIdx.z, b = bh >> 4, h = bh & 15;
    const int i0 = blockIdx.y << 7, j0 = blockIdx.x << 7;
    const int warp_m = (w >> 2) * 64, warp_n = (w & 3) * 32;
    const int am = tid >> 1, ako = (tid & 1) << 4;
    const int bkp = tid & 15, bcg = tid >> 4;
    float acc[4][4][4] = {};

    const float* kbase = g_K + (size_t)(b * SEQ + h * HD) * DM;  // k_t[dd][j]

    for (int k0 = 0; k0 < HD; k0 += 32) {
        store_rowmajor16(q_row(b, h, i0 + am) + k0 + ako, Ah, Al, am, ako >> 1);
        #pragma unroll
        for (int rep = 0; rep < 2; rep++) {
            const int c = (bcg + 16 * rep) << 2;
            const float* p = kbase + (size_t)(k0 + 2 * bkp) * DM + j0 + c;
            store_kmajor2x4(*(const float4*)p, *(const float4*)(p + DM), Bh, Bl, c, bkp);
        }
        __syncthreads();
        mma32<4, 4>(Ah, Al, Bh, Bl, acc, warp_m, warp_n, lane);
        __syncthreads();
    }
    const int qr = lane >> 2, qc = lane & 3;
    #pragma unroll
    for (int tm = 0; tm < 4; tm++)
        #pragma unroll
        for (int tn = 0; tn < 4; tn++)
            #pragma unroll
            for (int half = 0; half < 2; half++) {
                const int ig = i0 + warp_m + tm * 16 + qr + half * 8;
                #pragma unroll
                for (int e = 0; e < 2; e++) {
                    const int c = j0 + warp_n + tn * 8 + qc * 2 + e;
                    g_S[(size_t)(bh * SEQ + ig) * SEQ + c] =
                        (acc[tm][tn][half * 2 + e] + skew_rel(bh, ig, c)) * 0.125f;
                }
            }
}

// ---------------- row softmax over last dim of g_S ----------------
__global__ __launch_bounds__(256) void softmax_kernel()
{
    float* p = g_S + (size_t)blockIdx.x * SEQ;
    const int t = threadIdx.x;
    float x0 = p[t], x1 = p[t + 256], x2 = p[t + 512], x3 = p[t + 768];

    __shared__ float red[256];
    red[t] = fmaxf(fmaxf(x0, x1), fmaxf(x2, x3));
    __syncthreads();
    for (int s = 128; s > 0; s >>= 1) {
        if (t < s) red[t] = fmaxf(red[t], red[t + s]);
        __syncthreads();
    }
    const float m = red[0];
    __syncthreads();

    x0 = __expf(x0 - m); x1 = __expf(x1 - m); x2 = __expf(x2 - m); x3 = __expf(x3 - m);
    red[t] = x0 + x1 + x2 + x3;
    __syncthreads();
    for (int s = 128; s > 0; s >>= 1) {
        if (t < s) red[t] += red[t + s];
        __syncthreads();
    }
    const float inv = 1.0f / red[0];
    p[t] = x0 * inv; p[t + 256] = x1 * inv; p[t + 512] = x2 * inv; p[t + 768] = x3 * inv;
}

// ---------------- O[b, i, h*64+dd] = sum_j attn[bh,i,j] * v(b,h,j,dd) ----------------
__global__ __launch_bounds__(256) void av_tc()
{
    __shared__ unsigned Ah[128][20], Al[128][20];
    __shared__ unsigned Bh[64][20], Bl[64][20];
    const int tid = threadIdx.x, lane = tid & 31, w = tid >> 5;
    const int bh = blockIdx.y, b = bh >> 4, h = bh & 15;
    const int i0 = blockIdx.x << 7;
    const int warp_m = (w >> 2) * 64, warp_n = (w & 3) * 16;   // 2x4 warps, warp 64x16
    const int am = tid >> 1, ako = (tid & 1) << 4;
    const int bkp = tid & 15, bcg = tid >> 4;                  // 16 kpairs x 16 colgroups
    float acc[4][2][4] = {};

    for (int k0 = 0; k0 < SEQ; k0 += 32) {
        store_rowmajor16(g_S + (size_t)(bh * SEQ + i0 + am) * SEQ + k0 + ako, Ah, Al, am, ako >> 1);
        {
            const int c = bcg << 2;
            const float4 x0 = *(const float4*)(v_row(b, h, k0 + 2 * bkp) + c);
            const float4 x1 = *(const float4*)(v_row(b, h, k0 + 2 * bkp + 1) + c);
            store_kmajor2x4(x0, x1, Bh, Bl, c, bkp);
        }
        __syncthreads();
        mma32<4, 2>(Ah, Al, Bh, Bl, acc, warp_m, warp_n, lane);
        __syncthreads();
    }
    const int qr = lane >> 2, qc = lane & 3;
    #pragma unroll
    for (int tm = 0; tm < 4; tm++)
        #pragma unroll
        for (int tn = 0; tn < 2; tn++) {
            const int r = i0 + warp_m + tm * 16 + qr;
            const int cN = h * HD + warp_n + tn * 8 + qc * 2;
            *(float2*)(g_O + (size_t)(b * SEQ + r) * DM + cN)     = make_float2(acc[tm][tn][0], acc[tm][tn][1]);
            *(float2*)(g_O + (size_t)(b * SEQ + r + 8) * DM + cN) = make_float2(acc[tm][tn][2], acc[tm][tn][3]);
        }
}

// ---------------- launch ----------------
extern "C" void kernel_launch(void* const* d_in, const int* in_sizes, int n_in,
                              void* d_out, int out_size)
{
    const float* query = (const float*)d_in[0];
    const float* key   = (const float*)d_in[1];
    const float* value = (const float*)d_in[2];
    const float* WQ    = (const float*)d_in[3];
    const float* WK    = (const float*)d_in[4];
    const float* WV    = (const float*)d_in[5];
    const float* Er    = (const float*)d_in[6];
    const float* WM    = (const float*)d_in[7];
    float* out = (float*)d_out;

    static float *pQ = nullptr, *pK = nullptr, *pV = nullptr, *pO = nullptr;
    if (!pQ) {
        cudaGetSymbolAddress((void**)&pQ, g_Q);
        cudaGetSymbolAddress((void**)&pK, g_K);
        cudaGetSymbolAddress((void**)&pV, g_V);
        cudaGetSymbolAddress((void**)&pO, g_O);
    }

    const dim3 blk(256);
    const dim3 gProj(DM / 128, (BATCH * SEQ) / 128);   // (8, 32)
    const dim3 gHead(SEQ / 128, SEQ / 128, BH);        // (8, 8, 64)

    bf_gemm_nn<<<gProj, blk>>>(query, WQ, pQ, BATCH * SEQ, DM, DM);
    bf_gemm_nn<<<gProj, blk>>>(key,   WK, pK, BATCH * SEQ, DM, DM);
    bf_gemm_nn<<<gProj, blk>>>(value, WV, pV, BATCH * SEQ, DM, DM);
    qer_tc<<<gHead, blk>>>(Er);
    score_tc<<<gHead, blk>>>();
    softmax_kernel<<<BH * SEQ, blk>>>();
    av_tc<<<dim3(SEQ / 128, BH), blk>>>();
    bf_gemm_nn<<<gProj, blk>>>(pO, WM, out, BATCH * SEQ, DM, DM);
}

// round 6
// speedup vs baseline: 1.7027x; 1.4867x over previous
#include <cuda_runtime.h>
#include <cuda_bf16.h>

#define BATCH 4
#define SEQ   1024
#define DM    1024
#define HEADS 16
#define HD    64
#define BH    (BATCH*HEADS)

// ---------------- scratch (device globals; no allocs allowed) ----------------
__device__ float g_Q[BATCH*SEQ*DM];   // 16 MB
__device__ float g_K[BATCH*SEQ*DM];   // 16 MB
__device__ float g_V[BATCH*SEQ*DM];   // 16 MB
__device__ float g_O[BATCH*SEQ*DM];   // 16 MB

// ---------------- helpers ----------------
__device__ __forceinline__ void split2(float2 v, unsigned &h, unsigned &l) {
    __nv_bfloat162 bh = __float22bfloat162_rn(v);
    float2 back = __bfloat1622float2(bh);
    __nv_bfloat162 bl = __float22bfloat162_rn(make_float2(v.x - back.x, v.y - back.y));
    h = *(unsigned*)&bh;
    l = *(unsigned*)&bl;
}

__device__ __forceinline__ void mma_bf16(float c[4], const unsigned a[4], const unsigned b[2]) {
    asm volatile(
        "mma.sync.aligned.m16n8k16.row.col.f32.bf16.bf16.f32 "
        "{%0,%1,%2,%3},{%4,%5,%6,%7},{%8,%9},{%0,%1,%2,%3};\n"
        : "+f"(c[0]), "+f"(c[1]), "+f"(c[2]), "+f"(c[3])
        : "r"(a[0]), "r"(a[1]), "r"(a[2]), "r"(a[3]), "r"(b[0]), "r"(b[1]));
}

// store 16 consecutive k floats (row-major) as 8 packed bf16 pairs
// NOTE: pitch P multiple of 4 and p0 multiple of 4 keep uint4 stores 16B-aligned.
template<int P>
__device__ __forceinline__ void st_rm16(const float* src, unsigned (*H)[P], unsigned (*L)[P],
                                        int row, int p0) {
    unsigned h[8], l[8];
    #pragma unroll
    for (int i = 0; i < 4; i++) {
        const float4 x = *(const float4*)(src + 4 * i);
        split2(make_float2(x.x, x.y), h[2 * i], l[2 * i]);
        split2(make_float2(x.z, x.w), h[2 * i + 1], l[2 * i + 1]);
    }
    *(uint4*)&H[row][p0]     = make_uint4(h[0], h[1], h[2], h[3]);
    *(uint4*)&H[row][p0 + 4] = make_uint4(h[4], h[5], h[6], h[7]);
    *(uint4*)&L[row][p0]     = make_uint4(l[0], l[1], l[2], l[3]);
    *(uint4*)&L[row][p0 + 4] = make_uint4(l[4], l[5], l[6], l[7]);
}

template<int P>
__device__ __forceinline__ void st_rm16z(unsigned (*H)[P], unsigned (*L)[P], int row, int p0) {
    const uint4 z = make_uint4(0, 0, 0, 0);
    *(uint4*)&H[row][p0] = z; *(uint4*)&H[row][p0 + 4] = z;
    *(uint4*)&L[row][p0] = z; *(uint4*)&L[row][p0 + 4] = z;
}

// store a 2(k)x4(n) chunk from two k-rows into col-major B operand (scalar stores)
template<int P>
__device__ __forceinline__ void st_km2x4(float4 x0, float4 x1, unsigned (*H)[P],
                                         unsigned (*L)[P], int c, int kp) {
    unsigned h, l;
    split2(make_float2(x0.x, x1.x), h, l); H[c][kp] = h;     L[c][kp] = l;
    split2(make_float2(x0.y, x1.y), h, l); H[c + 1][kp] = h; L[c + 1][kp] = l;
    split2(make_float2(x0.z, x1.z), h, l); H[c + 2][kp] = h; L[c + 2][kp] = l;
    split2(make_float2(x0.w, x1.w), h, l); H[c + 3][kp] = h; L[c + 3][kp] = l;
}

// one k16 slab (pair base pb), TN n8-tiles, 3-term split MMA
template<int TN, int PA, int PB>
__device__ __forceinline__ void mma_k16_3(float (*acc)[4],
    const unsigned (*Ah)[PA], const unsigned (*Al)[PA],
    const unsigned (*Bh)[PB], const unsigned (*Bl)[PB],
    int arow, int pb, int qr, int qc)
{
    unsigned ah[4] = {Ah[arow + qr][pb + qc], Ah[arow + qr + 8][pb + qc],
                      Ah[arow + qr][pb + qc + 4], Ah[arow + qr + 8][pb + qc + 4]};
    unsigned al[4] = {Al[arow + qr][pb + qc], Al[arow + qr + 8][pb + qc],
                      Al[arow + qr][pb + qc + 4], Al[arow + qr + 8][pb + qc + 4]};
    #pragma unroll
    for (int tn = 0; tn < TN; tn++) {
        const int n = tn * 8 + qr;
        unsigned bh2[2] = {Bh[n][pb + qc], Bh[n][pb + qc + 4]};
        unsigned bl2[2] = {Bl[n][pb + qc], Bl[n][pb + qc + 4]};
        mma_bf16(acc[tn], ah, bh2);
        mma_bf16(acc[tn], al, bh2);
        mma_bf16(acc[tn], ah, bl2);
    }
}

__device__ __forceinline__ const float* q_row(int b, int h, int i) {
    return g_Q + (size_t)(b * SEQ + h * HD + (i >> 4)) * DM + ((i & 15) << 6);
}
__device__ __forceinline__ const float* v_row(int b, int h, int j) {
    return g_V + (size_t)(b * SEQ + h * HD + (j >> 4)) * DM + ((j & 15) << 6);
}

// ==================== projection / merge GEMM (round-3 proven) ====================
__device__ __forceinline__ void mma32p(const unsigned (*Ah)[20], const unsigned (*Al)[20],
                                       const unsigned (*Bh)[20], const unsigned (*Bl)[20],
                                       float (*acc)[4][4], int warp_m, int warp_n, int lane) {
    const int qr = lane >> 2, qc = lane & 3;
    #pragma unroll
    for (int s = 0; s < 2; s++) {
        const int kp = qc + 8 * s;
        unsigned ah[4][4], al[4][4], bh[4][2], bl[4][2];
        #pragma unroll
        for (int tm = 0; tm < 4; tm++) {
            const int m = warp_m + tm * 16 + qr;
            ah[tm][0] = Ah[m][kp];     ah[tm][1] = Ah[m + 8][kp];
            ah[tm][2] = Ah[m][kp + 4]; ah[tm][3] = Ah[m + 8][kp + 4];
            al[tm][0] = Al[m][kp];     al[tm][1] = Al[m + 8][kp];
            al[tm][2] = Al[m][kp + 4]; al[tm][3] = Al[m + 8][kp + 4];
        }
        #pragma unroll
        for (int tn = 0; tn < 4; tn++) {
            const int n = warp_n + tn * 8 + qr;
            bh[tn][0] = Bh[n][kp]; bh[tn][1] = Bh[n][kp + 4];
            bl[tn][0] = Bl[n][kp]; bl[tn][1] = Bl[n][kp + 4];
        }
        #pragma unroll
        for (int tm = 0; tm < 4; tm++)
            #pragma unroll
            for (int tn = 0; tn < 4; tn++) {
                mma_bf16(acc[tm][tn], ah[tm], bh[tn]);
                mma_bf16(acc[tm][tn], al[tm], bh[tn]);
                mma_bf16(acc[tm][tn], ah[tm], bl[tn]);
            }
    }
}

__global__ __launch_bounds__(256, 2) void bf_gemm_nn(const float* __restrict__ A,
                                                     const float* __restrict__ W,
                                                     float* __restrict__ C,
                                                     int M, int N, int K)
{
    __shared__ unsigned Ah[128][20], Al[128][20], Bh[128][20], Bl[128][20];
    const int tid = threadIdx.x, lane = tid & 31, w = tid >> 5;
    const int m0 = blockIdx.y << 7, n0 = blockIdx.x << 7;
    const int warp_m = (w >> 2) * 64, warp_n = (w & 3) * 32;
    const int am = tid >> 1, ako = (tid & 1) << 4;
    const int bkp = tid & 15, bcg = tid >> 4;
    float acc[4][4][4] = {};

    for (int k0 = 0; k0 < K; k0 += 32) {
        st_rm16<20>(A + (size_t)(m0 + am) * K + k0 + ako, Ah, Al, am, ako >> 1);
        #pragma unroll
        for (int rep = 0; rep < 2; rep++) {
            const int c = (bcg + 16 * rep) << 2;
            const float* p = W + (size_t)(k0 + 2 * bkp) * N + n0 + c;
            st_km2x4<20>(*(const float4*)p, *(const float4*)(p + N), Bh, Bl, c, bkp);
        }
        __syncthreads();
        mma32p(Ah, Al, Bh, Bl, acc, warp_m, warp_n, lane);
        __syncthreads();
    }
    const int qr = lane >> 2, qc = lane & 3;
    #pragma unroll
    for (int tm = 0; tm < 4; tm++)
        #pragma unroll
        for (int tn = 0; tn < 4; tn++) {
            const int r = m0 + warp_m + tm * 16 + qr;
            const int cN = n0 + warp_n + tn * 8 + qc * 2;
            *(float2*)(C + (size_t)r * N + cN)       = make_float2(acc[tm][tn][0], acc[tm][tn][1]);
            *(float2*)(C + (size_t)(r + 8) * N + cN) = make_float2(acc[tm][tn][2], acc[tm][tn][3]);
        }
}

// ==================== fused flash attention with relative bias ====================
// Pitches: 36 for Q/K/E (36 ≡ 4 mod 32 → conflict-free fragment loads, 16B-aligned rows),
//          68 for V/P (same properties).
struct FSmem {
    unsigned Qh[129][36], Ql[129][36];   // Q rows i0..i0+128 (129 for the +1 shift)
    unsigned Kh[128][36], Kl[128][36];   // K^T tile: [j][dd-pair]
    unsigned Eh[128][36], El[128][36];   // Er window: [e][dd-pair]
    unsigned Vh[64][68],  Vl[64][68];    // V tile: [dd][j-pair]
    union {
        float G[128][132];                        // rel-bias staging
        struct { unsigned Ph[128][68], Pl[128][68]; } pp;  // softmaxed P operand
    } u;
};

__global__ __launch_bounds__(256, 1) void flash_kernel(const float* __restrict__ Er)
{
    extern __shared__ char raw[];
    FSmem* sm = (FSmem*)raw;
    const int tid = threadIdx.x, lane = tid & 31, w = tid >> 5;
    const int qr = lane >> 2, qc = lane & 3;
    const int bh = blockIdx.y, b = bh >> 4, h = bh & 15;
    const int i0 = blockIdx.x << 7;

    // ---- load Q: 129 rows x 64 floats = 129*4 chunks of 16 floats ----
    #pragma unroll
    for (int it = 0; it < 3; it++) {
        const int idx = tid + it * 256;
        if (idx < 129 * 4) {
            const int r = idx >> 2, ch = idx & 3;
            if (i0 + r < SEQ) st_rm16<36>(q_row(b, h, i0 + r) + ch * 16, sm->Qh, sm->Ql, r, ch * 8);
            else              st_rm16z<36>(sm->Qh, sm->Ql, r, ch * 8);
        }
    }

    float accO[8][4] = {};
    float m0 = -1e30f, m1 = -1e30f, l0 = 0.f, l1 = 0.f;
    const float* kbase = g_K + (size_t)(b * SEQ + h * HD) * DM;

    for (int jt = 0; jt < 8; jt++) {
        const int j0 = jt << 7;
        const int delta = j0 - i0;
        float accS[16][4] = {};

        // ---- relative-bias phases: G = Q(+shift) @ ErWindow^T, then diagonal gather ----
        #pragma unroll 1
        for (int band = 0; band < 2; band++) {       // 0 = lower (c<=i), 1 = upper (c>=i+2)
            if (band == 0 && delta > 0) continue;
            if (band == 1 && delta < 0) continue;
            const int ebase = (band == 0) ? (895 + delta) : (delta - 130);
            #pragma unroll 1
            for (int half = 0; half < 2; half++) {
                if (band == 1 && half == 0 && delta < 128) continue;
                // load Er window half: 128 rows x 4 chunks (zero-fill OOB; never gathered)
                #pragma unroll
                for (int it = 0; it < 2; it++) {
                    const int idx = tid + it * 256;
                    const int r = idx >> 2, ch = idx & 3;
                    const int er = ebase + half * 128 + r;
                    if (er >= 0 && er < SEQ)
                        st_rm16<36>(Er + (size_t)er * HD + ch * 16, sm->Eh, sm->El, r, ch * 8);
                    else
                        st_rm16z<36>(sm->Eh, sm->El, r, ch * 8);
                }
                __syncthreads();   // E ready; also frees P/V from prior tile's MMA reads
                float gacc[16][4] = {};
                const int arow = w * 16 + band;      // upper band uses q_{i+1}
                #pragma unroll
                for (int pb = 0; pb < 32; pb += 8)
                    mma_k16_3<16, 36, 36>(gacc, sm->Qh, sm->Ql, sm->Eh, sm->El, arow, pb, qr, qc);
                #pragma unroll
                for (int tn = 0; tn < 16; tn++) {
                    const int r = w * 16 + qr, c = tn * 8 + qc * 2;
                    *(float2*)&sm->u.G[r][c]     = make_float2(gacc[tn][0], gacc[tn][1]);
                    *(float2*)&sm->u.G[r + 8][c] = make_float2(gacc[tn][2], gacc[tn][3]);
                }
                __syncthreads();
                #pragma unroll
                for (int tn = 0; tn < 16; tn++)
                    #pragma unroll
                    for (int k = 0; k < 4; k++) {
                        const int r = w * 16 + qr + ((k >> 1) << 3);
                        const int jc = tn * 8 + qc * 2 + (k & 1);
                        const int diff = jc - r;
                        const bool cond = (band == 0) ? (diff <= -delta) : (diff >= 2 - delta);
                        const int mm = 128 + diff - half * 128;
                        if (cond && mm >= 0 && mm < 128) accS[tn][k] += sm->u.G[r][mm];
                    }
            }
        }

        // ---- load K^T and V tiles ----
        #pragma unroll
        for (int it = 0; it < 4; it++) {
            const int idx = tid + it * 256;
            const int kp = idx & 31, cg = idx >> 5;
            const float* p = kbase + (size_t)(2 * kp) * DM + j0 + cg * 4;
            st_km2x4<36>(*(const float4*)p, *(const float4*)(p + DM), sm->Kh, sm->Kl, cg * 4, kp);
        }
        #pragma unroll
        for (int it = 0; it < 4; it++) {
            const int idx = tid + it * 256;
            const int jp = idx & 63, cg = idx >> 6;
            const float4 x0 = *(const float4*)(v_row(b, h, j0 + 2 * jp)     + cg * 4);
            const float4 x1 = *(const float4*)(v_row(b, h, j0 + 2 * jp + 1) + cg * 4);
            st_km2x4<68>(x0, x1, sm->Vh, sm->Vl, cg * 4, jp);
        }
        __syncthreads();   // K,V ready; all gathers done (G region free for P)

        // ---- q @ k^T accumulate on top of rel ----
        #pragma unroll
        for (int pb = 0; pb < 32; pb += 8)
            mma_k16_3<16, 36, 36>(accS, sm->Qh, sm->Ql, sm->Kh, sm->Kl, w * 16, pb, qr, qc);

        // ---- online softmax (logits = accS * 0.125) ----
        float tm0 = -1e30f, tm1 = -1e30f;
        #pragma unroll
        for (int tn = 0; tn < 16; tn++) {
            tm0 = fmaxf(tm0, fmaxf(accS[tn][0], accS[tn][1]));
            tm1 = fmaxf(tm1, fmaxf(accS[tn][2], accS[tn][3]));
        }
        tm0 = fmaxf(tm0, __shfl_xor_sync(0xffffffffu, tm0, 1));
        tm0 = fmaxf(tm0, __shfl_xor_sync(0xffffffffu, tm0, 2));
        tm1 = fmaxf(tm1, __shfl_xor_sync(0xffffffffu, tm1, 1));
        tm1 = fmaxf(tm1, __shfl_xor_sync(0xffffffffu, tm1, 2));
        tm0 *= 0.125f; tm1 *= 0.125f;
        const float nm0 = fmaxf(m0, tm0), nm1 = fmaxf(m1, tm1);
        const float f0 = __expf(m0 - nm0), f1 = __expf(m1 - nm1);
        float s0 = 0.f, s1 = 0.f;
        #pragma unroll
        for (int tn = 0; tn < 16; tn++) {
            accS[tn][0] = __expf(accS[tn][0] * 0.125f - nm0); s0 += accS[tn][0];
            accS[tn][1] = __expf(accS[tn][1] * 0.125f - nm0); s0 += accS[tn][1];
            accS[tn][2] = __expf(accS[tn][2] * 0.125f - nm1); s1 += accS[tn][2];
            accS[tn][3] = __expf(accS[tn][3] * 0.125f - nm1); s1 += accS[tn][3];
        }
        s0 += __shfl_xor_sync(0xffffffffu, s0, 1); s0 += __shfl_xor_sync(0xffffffffu, s0, 2);
        s1 += __shfl_xor_sync(0xffffffffu, s1, 1); s1 += __shfl_xor_sync(0xffffffffu, s1, 2);
        l0 = l0 * f0 + s0; l1 = l1 * f1 + s1; m0 = nm0; m1 = nm1;
        #pragma unroll
        for (int tn2 = 0; tn2 < 8; tn2++) {
            accO[tn2][0] *= f0; accO[tn2][1] *= f0;
            accO[tn2][2] *= f1; accO[tn2][3] *= f1;
        }

        // ---- write split-bf16 P operand ----
        #pragma unroll
        for (int tn = 0; tn < 16; tn++) {
            unsigned hh, ll;
            split2(make_float2(accS[tn][0], accS[tn][1]), hh, ll);
            sm->u.pp.Ph[w * 16 + qr][tn * 4 + qc] = hh;
            sm->u.pp.Pl[w * 16 + qr][tn * 4 + qc] = ll;
            split2(make_float2(accS[tn][2], accS[tn][3]), hh, ll);
            sm->u.pp.Ph[w * 16 + qr + 8][tn * 4 + qc] = hh;
            sm->u.pp.Pl[w * 16 + qr + 8][tn * 4 + qc] = ll;
        }
        __syncthreads();

        // ---- accO += P @ V ----
        #pragma unroll
        for (int pb = 0; pb < 64; pb += 8)
            mma_k16_3<8, 68, 68>(accO, sm->u.pp.Ph, sm->u.pp.Pl, sm->Vh, sm->Vl, w * 16, pb, qr, qc);
        // next tile's first __syncthreads (after E load) protects P/V reuse
    }

    // ---- epilogue: normalize and write O[b, i, h*64+dd] ----
    const float inv0 = 1.f / l0, inv1 = 1.f / l1;
    #pragma unroll
    for (int tn2 = 0; tn2 < 8; tn2++) {
        const int r = i0 + w * 16 + qr;
        const int col = h * HD + tn2 * 8 + qc * 2;
        *(float2*)(g_O + (size_t)(b * SEQ + r) * DM + col) =
            make_float2(accO[tn2][0] * inv0, accO[tn2][1] * inv0);
        *(float2*)(g_O + (size_t)(b * SEQ + r + 8) * DM + col) =
            make_float2(accO[tn2][2] * inv1, accO[tn2][3] * inv1);
    }
}

// ---------------- launch ----------------
extern "C" void kernel_launch(void* const* d_in, const int* in_sizes, int n_in,
                              void* d_out, int out_size)
{
    const float* query = (const float*)d_in[0];
    const float* key   = (const float*)d_in[1];
    const float* value = (const float*)d_in[2];
    const float* WQ    = (const float*)d_in[3];
    const float* WK    = (const float*)d_in[4];
    const float* WV    = (const float*)d_in[5];
    const float* Er    = (const float*)d_in[6];
    const float* WM    = (const float*)d_in[7];
    float* out = (float*)d_out;

    static float *pQ = nullptr, *pK = nullptr, *pV = nullptr, *pO = nullptr;
    if (!pQ) {
        cudaGetSymbolAddress((void**)&pQ, g_Q);
        cudaGetSymbolAddress((void**)&pK, g_K);
        cudaGetSymbolAddress((void**)&pV, g_V);
        cudaGetSymbolAddress((void**)&pO, g_O);
        cudaFuncSetAttribute(flash_kernel, cudaFuncAttributeMaxDynamicSharedMemorySize,
                             (int)sizeof(FSmem));
    }

    const dim3 blk(256);
    const dim3 gProj(DM / 128, (BATCH * SEQ) / 128);   // (8, 32)

    bf_gemm_nn<<<gProj, blk>>>(query, WQ, pQ, BATCH * SEQ, DM, DM);
    bf_gemm_nn<<<gProj, blk>>>(key,   WK, pK, BATCH * SEQ, DM, DM);
    bf_gemm_nn<<<gProj, blk>>>(value, WV, pV, BATCH * SEQ, DM, DM);
    flash_kernel<<<dim3(SEQ / 128, BH), blk, sizeof(FSmem)>>>(Er);
    bf_gemm_nn<<<gProj, blk>>>(pO, WM, out, BATCH * SEQ, DM, DM);
}